// round 15
// baseline (speedup 1.0000x reference)
#include <cuda_runtime.h>
#include <cuda_fp16.h>
#include <cstdint>

// Problem constants
#define BATCH 4
#define SEQ   4096
#define DIM   1024
#define NHEAD 16
#define HDIM  64
#define WIN   256
#define EXT   128
#define NGRP  (SEQ / WIN)          // 16
#define QKVDIM (3 * DIM)           // 3072
#define MROWS (BATCH * SEQ)        // 16384
#define ATT_SCALE 0.125f           // 64^-0.5

// ---------------- scratch (allocation-free: __device__ globals) ----------------
__device__ __half g_qkvh[(size_t)MROWS * QKVDIM];   // 96 MB
__device__ __half g_xh[(size_t)MROWS * DIM];        // 32 MB
__device__ __half g_wqkvh[(size_t)QKVDIM * DIM];    // 6 MB
__device__ __half g_attnh[(size_t)MROWS * DIM];     // 32 MB
__device__ __half g_wprojh[(size_t)DIM * DIM];      // 2 MB

// ================= PTX helpers (base sm_103: NO 'a'-gated instructions) =================
__device__ __forceinline__ uint32_t smem_u32(const void* p) {
    uint32_t a;
    asm("{ .reg .u64 t; cvta.to.shared.u64 t, %1; cvt.u32.u64 %0, t; }" : "=r"(a) : "l"(p));
    return a;
}
#define CP_ASYNC16(s, g) \
    asm volatile("cp.async.cg.shared.global [%0], [%1], 16;" :: "r"(s), "l"(g))
#define CP_COMMIT() asm volatile("cp.async.commit_group;" ::: "memory")
#define CP_WAIT_GROUP(n) asm volatile("cp.async.wait_group %0;" :: "n"(n) : "memory")

__device__ __forceinline__ void ldm_x4(uint32_t* r, uint32_t a) {
    asm volatile("ldmatrix.sync.aligned.m8n8.x4.shared.b16 {%0,%1,%2,%3}, [%4];"
                 : "=r"(r[0]), "=r"(r[1]), "=r"(r[2]), "=r"(r[3]) : "r"(a));
}
__device__ __forceinline__ void ldm_x4_t(uint32_t* r, uint32_t a) {
    asm volatile("ldmatrix.sync.aligned.m8n8.x4.trans.shared.b16 {%0,%1,%2,%3}, [%4];"
                 : "=r"(r[0]), "=r"(r[1]), "=r"(r[2]), "=r"(r[3]) : "r"(a));
}
__device__ __forceinline__ void mma_f16(float* d, const uint32_t* a, const uint32_t* b) {
    asm volatile("mma.sync.aligned.m16n8k16.row.col.f32.f16.f16.f32 "
                 "{%0,%1,%2,%3}, {%4,%5,%6,%7}, {%8,%9}, {%0,%1,%2,%3};"
                 : "+f"(d[0]), "+f"(d[1]), "+f"(d[2]), "+f"(d[3])
                 : "r"(a[0]), "r"(a[1]), "r"(a[2]), "r"(a[3]), "r"(b[0]), "r"(b[1]));
}
__device__ __forceinline__ uint32_t pack2(float a, float b) {
    __half2 h = __floats2half2_rn(a, b);
    return *(uint32_t*)&h;
}

// ---------------- fused convert fp32 -> fp16 (x, w_qkv, w_proj in one grid) ----
#define CVT_N4_X   (MROWS * DIM / 4)          // 4194304
#define CVT_N4_WQ  (QKVDIM * DIM / 4)         // 786432
#define CVT_N4_WP  (DIM * DIM / 4)            // 262144
#define CVT_N4_ALL (CVT_N4_X + CVT_N4_WQ + CVT_N4_WP)

__global__ void k_cvt3(const float* __restrict__ x, const float* __restrict__ wq,
                       const float* __restrict__ wp, __half* __restrict__ xo,
                       __half* __restrict__ wqo, __half* __restrict__ wpo) {
    int i = blockIdx.x * blockDim.x + threadIdx.x;
    const float* in;
    __half* out;
    int j = i;
    if (j < CVT_N4_X) { in = x; out = xo; }
    else if ((j -= CVT_N4_X) < CVT_N4_WQ) { in = wq; out = wqo; }
    else if ((j -= CVT_N4_WQ) < CVT_N4_WP) { in = wp; out = wpo; }
    else return;
    float4 v = ((const float4*)in)[j];
    ((uint2*)out)[j] = make_uint2(pack2(v.x, v.y), pack2(v.z, v.w));
}

// ---------------- HMMA fp16 GEMM ----------------
// C = A[M][K] * B[N][K]^T + bias. 128x128 CTA tile, K-chunk 64,
// 8 warps (2Mx4N, warp 64x32), 3-stage cp.async ring, 2 CTAs/SM.
// Mainloop software-pipelines fragment LDSMs one ks-step ahead of the MMAs
// (asm volatile fixes issue order, so the distance must be explicit).
#define GT_TILE   16384                       // one 128x64 fp16 tile
#define GT_BUF    (2 * GT_TILE)               // A + B = 32 KB per stage
#define GT_STAGES 3
#define GT_TOTAL  (GT_STAGES * GT_BUF)        // 96 KB

template <bool HALF_OUT>
__global__ __launch_bounds__(256, 2) void k_gemm_hmma(
    const __half* __restrict__ A, const __half* __restrict__ B,
    const float* __restrict__ bias, float* __restrict__ C,
    __half* __restrict__ Ch, int M, int N, int K) {
    extern __shared__ char smem[];
    const uint32_t sb = smem_u32(smem);
    const int tid = threadIdx.x;
    const int wid = tid >> 5, l = tid & 31;
    const int bm = blockIdx.y * 128;
    const int bn = blockIdx.x * 128;
    const int wm = (wid >> 2) * 64;
    const int wn = (wid & 3) * 32;

    float acc[4][4][4];
    #pragma unroll
    for (int a = 0; a < 4; a++)
        #pragma unroll
        for (int b = 0; b < 4; b++)
            #pragma unroll
            for (int c = 0; c < 4; c++) acc[a][b][c] = 0.f;

    const int NCH = K >> 6;                   // chunks of 64

    // precomputed per-lane fragment geometry
    const int ar_l = wm + ((l >> 3) & 1) * 8 + (l & 7);
    const int a_ch = l >> 4;                  // k-half for A frags
    const int m_ = l >> 3;
    const int brow = wn + (m_ >> 1) * 8 + (l & 7);
    const int b_ch = m_ & 1;                  // k-half for B frags

    auto load_chunk = [&](int c, int buf) {
        const int k0 = c * 64;
        const uint32_t sbase = sb + buf * GT_BUF;
        #pragma unroll
        for (int j = 0; j < 8; j++) {
            int i = tid + j * 256;            // 0..2047
            int t = i >> 10;                  // 0 = A, 1 = B
            int idx = i & 1023;
            int row = idx >> 3, ch = idx & 7;
            uint32_t soff = row * 128 + ((ch ^ (row & 7)) << 4);
            const __half* src = (t ? B : A)
                + (size_t)((t ? bn : bm) + row) * K + k0 + ch * 8;
            CP_ASYNC16(sbase + t * GT_TILE + soff, src);
        }
    };

    auto compute = [&](int buf) {
        const uint32_t sbase = sb + buf * GT_BUF;
        uint32_t ah[2][4][4], bf[2][2][4];    // double-buffered fragments
        auto ldfrags = [&](int ks, int pb) {
            const int ach = 2 * ks + a_ch;
            #pragma unroll
            for (int mf = 0; mf < 4; mf++) {
                int r = ar_l + mf * 16;
                ldm_x4(ah[pb][mf], sbase + r * 128 + ((ach ^ (r & 7)) << 4));
            }
            const int bch = 2 * ks + b_ch;
            #pragma unroll
            for (int np = 0; np < 2; np++) {
                int r = brow + np * 16;
                ldm_x4(bf[np ? 1 : 0][np] /*dummy idx fix below*/, 0); // placeholder
            }
        };
        // (ldfrags defined inline below to keep indices right)
        auto ldf = [&](int ks, int pb) {
            const int ach = 2 * ks + a_ch;
            #pragma unroll
            for (int mf = 0; mf < 4; mf++) {
                int r = ar_l + mf * 16;
                ldm_x4(ah[pb][mf], sbase + r * 128 + ((ach ^ (r & 7)) << 4));
            }
            const int bch = 2 * ks + b_ch;
            #pragma unroll
            for (int np = 0; np < 2; np++) {
                int r = brow + np * 16;
                ldm_x4(bf[pb][np], sbase + GT_TILE + r * 128 + ((bch ^ (r & 7)) << 4));
            }
        };
        (void)ldfrags;
        ldf(0, 0);
        #pragma unroll
        for (int ks = 0; ks < 4; ks++) {
            if (ks < 3) ldf(ks + 1, (ks + 1) & 1);   // prefetch next step's frags
            const int pb = ks & 1;
            #pragma unroll
            for (int mf = 0; mf < 4; mf++)
                #pragma unroll
                for (int np = 0; np < 2; np++) {
                    mma_f16(acc[mf][2 * np],     ah[pb][mf], bf[pb][np]);
                    mma_f16(acc[mf][2 * np + 1], ah[pb][mf], bf[pb][np] + 2);
                }
        }
    };

    load_chunk(0, 0);
    CP_COMMIT();
    load_chunk(1, 1);
    CP_COMMIT();
    for (int c = 0; c < NCH; c++) {
        CP_WAIT_GROUP(1);
        __syncthreads();
        if (c + 2 < NCH) load_chunk(c + 2, (c + 2) % 3);
        CP_COMMIT();
        compute(c % 3);
    }

    const int rbase = bm + wm + (l >> 2);
    const int cbase = bn + wn + (l & 3) * 2;
    #pragma unroll
    for (int mf = 0; mf < 4; mf++) {
        int r0 = rbase + mf * 16;
        #pragma unroll
        for (int nf = 0; nf < 4; nf++) {
            int cc = cbase + nf * 8;
            float2 bv = *(const float2*)&bias[cc];
            float v00 = acc[mf][nf][0] + bv.x, v01 = acc[mf][nf][1] + bv.y;
            float v10 = acc[mf][nf][2] + bv.x, v11 = acc[mf][nf][3] + bv.y;
            if (HALF_OUT) {
                *(uint32_t*)(Ch + (size_t)r0 * N + cc) = pack2(v00, v01);
                *(uint32_t*)(Ch + (size_t)(r0 + 8) * N + cc) = pack2(v10, v11);
            } else {
                *(float2*)&C[(size_t)r0 * N + cc] = make_float2(v00, v01);
                *(float2*)&C[(size_t)(r0 + 8) * N + cc] = make_float2(v10, v11);
            }
        }
    }
}

// ---------------- HMMA local attention (fp16) ----------------
// CTA = 128 q rows of one (b,h,group-half). 8 warps x 16 q rows.
// 3-stage KV ring (16 KB/stage), one barrier per 64-key chunk. 2 CTAs/SM.
#define AT_SMEM (16384 + 3 * 16384)

__global__ __launch_bounds__(256, 2) void k_attn_hmma(
    const __half* __restrict__ qg, __half* __restrict__ og) {
    extern __shared__ char smem[];
    const uint32_t sb = smem_u32(smem);
    const int half_ = blockIdx.x & 1, g = blockIdx.x >> 1;
    const int h = blockIdx.y, b = blockIdx.z;
    const int tid = threadIdx.x, wid = tid >> 5, l = tid & 31;
    const int qrow0 = b * SEQ + g * WIN + half_ * 128;
    const int wq = wid * 16;

    #pragma unroll
    for (int j = 0; j < 4; j++) {
        int idx = tid + j * 256;
        int row = idx >> 3, ch = idx & 7;
        const __half* src = qg + (size_t)(qrow0 + row) * QKVDIM + h * HDIM + ch * 8;
        CP_ASYNC16(sb + row * 128 + ((ch ^ (row & 7)) << 4), src);
    }

    auto stage_kv = [&](int c, int buf) {
        const int kr0 = b * SEQ + g * WIN - EXT + c * 64;
        const uint32_t base = sb + 16384 + buf * 16384;
        #pragma unroll
        for (int j = 0; j < 4; j++) {
            int i = tid + j * 256;
            int t = i >> 9;                   // 0 = K, 1 = V
            int idx = i & 511;
            int row = idx >> 3, ch = idx & 7;
            const __half* src = qg + (size_t)(kr0 + row) * QKVDIM
                + (t ? 2 * DIM : DIM) + h * HDIM + ch * 8;
            CP_ASYNC16(base + t * 8192 + row * 128 + ((ch ^ (row & 7)) << 4), src);
        }
    };

    uint32_t qf[4][4];
    float o[8][4];
    #pragma unroll
    for (int nf = 0; nf < 8; nf++)
        #pragma unroll
        for (int j = 0; j < 4; j++) o[nf][j] = 0.f;
    float ma = -1e30f, mb = -1e30f, la = 0.f, lb = 0.f;

    const int c0 = (g == 0) ? 2 : 0;
    const int c1 = (g == NGRP - 1) ? 6 : 8;
    const int nch = c1 - c0;

    stage_kv(c0, 0);
    CP_COMMIT();
    if (nch > 1) stage_kv(c0 + 1, 1);
    CP_COMMIT();

    for (int it = 0; it < nch; it++) {
        CP_WAIT_GROUP(1);
        __syncthreads();
        {
            int nxt = it + 2;
            if (nxt < nch) stage_kv(c0 + nxt, nxt % 3);
            CP_COMMIT();
        }
        if (it == 0) {
            #pragma unroll
            for (int ks = 0; ks < 4; ks++) {
                int r = wq + (l & 7) + ((l >> 3) & 1) * 8;
                int c = 2 * ks + ((l >> 4) & 1);
                ldm_x4(qf[ks], sb + r * 128 + ((c ^ (r & 7)) << 4));
            }
        }
        const uint32_t kb = sb + 16384 + (it % 3) * 16384;

        // ---- QK: S[16q x 64k] per warp ----
        float s[8][4];
        #pragma unroll
        for (int nf = 0; nf < 8; nf++)
            #pragma unroll
            for (int j = 0; j < 4; j++) s[nf][j] = 0.f;
        #pragma unroll
        for (int ks = 0; ks < 4; ks++) {
            const int r = (l & 7) + ((l >> 4) & 1) * 8;
            const int c = 2 * ks + ((l >> 3) & 1);
            #pragma unroll
            for (int np = 0; np < 4; np++) {
                int rr = np * 16 + r;
                uint32_t kf[4];
                ldm_x4(kf, kb + rr * 128 + ((c ^ (rr & 7)) << 4));
                mma_f16(s[2 * np],     qf[ks], kf);
                mma_f16(s[2 * np + 1], qf[ks], kf + 2);
            }
        }

        // ---- online softmax ----
        float mxa = -1e30f, mxb = -1e30f;
        #pragma unroll
        for (int nf = 0; nf < 8; nf++) {
            mxa = fmaxf(mxa, fmaxf(s[nf][0], s[nf][1]));
            mxb = fmaxf(mxb, fmaxf(s[nf][2], s[nf][3]));
        }
        mxa = fmaxf(mxa, __shfl_xor_sync(0xffffffffu, mxa, 1));
        mxa = fmaxf(mxa, __shfl_xor_sync(0xffffffffu, mxa, 2));
        mxb = fmaxf(mxb, __shfl_xor_sync(0xffffffffu, mxb, 1));
        mxb = fmaxf(mxb, __shfl_xor_sync(0xffffffffu, mxb, 2));
        float nma = fmaxf(ma, mxa), nmb = fmaxf(mb, mxb);
        float ca = __expf((ma - nma) * ATT_SCALE);
        float cb = __expf((mb - nmb) * ATT_SCALE);
        ma = nma; mb = nmb;
        la *= ca; lb *= cb;
        #pragma unroll
        for (int nf = 0; nf < 8; nf++) {
            s[nf][0] = __expf((s[nf][0] - ma) * ATT_SCALE);
            s[nf][1] = __expf((s[nf][1] - ma) * ATT_SCALE);
            s[nf][2] = __expf((s[nf][2] - mb) * ATT_SCALE);
            s[nf][3] = __expf((s[nf][3] - mb) * ATT_SCALE);
            la += s[nf][0] + s[nf][1];
            lb += s[nf][2] + s[nf][3];
            o[nf][0] *= ca; o[nf][1] *= ca;
            o[nf][2] *= cb; o[nf][3] *= cb;
        }

        // ---- pack P into A-frags ----
        uint32_t pf[4][4];
        #pragma unroll
        for (int j = 0; j < 4; j++) {
            pf[j][0] = pack2(s[2 * j][0],     s[2 * j][1]);
            pf[j][1] = pack2(s[2 * j][2],     s[2 * j][3]);
            pf[j][2] = pack2(s[2 * j + 1][0], s[2 * j + 1][1]);
            pf[j][3] = pack2(s[2 * j + 1][2], s[2 * j + 1][3]);
        }

        // ---- PV: O += P * V ----
        #pragma unroll
        for (int ks = 0; ks < 4; ks++) {
            const int r = ks * 16 + (l & 7) + ((l >> 3) & 1) * 8;
            const int c = (l >> 4) & 1;
            #pragma unroll
            for (int dp = 0; dp < 4; dp++) {
                int cc = 2 * dp + c;
                uint32_t vf[4];
                ldm_x4_t(vf, kb + 8192 + r * 128 + ((cc ^ (r & 7)) << 4));
                mma_f16(o[2 * dp],     pf[ks], vf);
                mma_f16(o[2 * dp + 1], pf[ks], vf + 2);
            }
        }
    }

    // ---- epilogue ----
    la += __shfl_xor_sync(0xffffffffu, la, 1);
    la += __shfl_xor_sync(0xffffffffu, la, 2);
    lb += __shfl_xor_sync(0xffffffffu, lb, 1);
    lb += __shfl_xor_sync(0xffffffffu, lb, 2);
    const float ia = 1.f / la, ib = 1.f / lb;
    const int ra = qrow0 + wq + (l >> 2);
    const int rb = ra + 8;
    const int colb = h * HDIM + 2 * (l & 3);
    #pragma unroll
    for (int nf = 0; nf < 8; nf++) {
        int cc = colb + nf * 8;
        *(uint32_t*)(og + (size_t)ra * DIM + cc) = pack2(o[nf][0] * ia, o[nf][1] * ia);
        *(uint32_t*)(og + (size_t)rb * DIM + cc) = pack2(o[nf][2] * ib, o[nf][3] * ib);
    }
}

// ---------------- launch ----------------
extern "C" void kernel_launch(void* const* d_in, const int* in_sizes, int n_in,
                              void* d_out, int out_size) {
    const float* x      = (const float*)d_in[0];
    const float* w_qkv  = (const float*)d_in[1];
    const float* b_qkv  = (const float*)d_in[2];
    const float* w_proj = (const float*)d_in[3];
    const float* b_proj = (const float*)d_in[4];
    float* out = (float*)d_out;

    __half *qh, *xh, *wqh, *ah, *wph;
    cudaGetSymbolAddress((void**)&qh,  g_qkvh);
    cudaGetSymbolAddress((void**)&xh,  g_xh);
    cudaGetSymbolAddress((void**)&wqh, g_wqkvh);
    cudaGetSymbolAddress((void**)&ah,  g_attnh);
    cudaGetSymbolAddress((void**)&wph, g_wprojh);

    cudaFuncSetAttribute(k_gemm_hmma<true>,  cudaFuncAttributeMaxDynamicSharedMemorySize, GT_TOTAL);
    cudaFuncSetAttribute(k_gemm_hmma<false>, cudaFuncAttributeMaxDynamicSharedMemorySize, GT_TOTAL);
    cudaFuncSetAttribute(k_attn_hmma, cudaFuncAttributeMaxDynamicSharedMemorySize, AT_SMEM);

    // 1. fused fp32 -> fp16 converts
    k_cvt3<<<(CVT_N4_ALL + 255) / 256, 256>>>(x, w_qkv, w_proj, xh, wqh, wph);

    // 2. QKV projection -> fp16
    k_gemm_hmma<true><<<dim3(QKVDIM / 128, MROWS / 128), 256, GT_TOTAL>>>(
        xh, wqh, b_qkv, nullptr, qh, MROWS, QKVDIM, DIM);

    // 3. local windowed attention -> fp16
    k_attn_hmma<<<dim3(NGRP * 2, NHEAD, BATCH), 256, AT_SMEM>>>(qh, ah);

    // 4. output projection -> fp32 out
    k_gemm_hmma<false><<<dim3(DIM / 128, MROWS / 128), 256, GT_TOTAL>>>(
        ah, wph, b_proj, out, nullptr, MROWS, DIM, DIM);
}

// round 17
// speedup vs baseline: 1.0601x; 1.0601x over previous
#include <cuda_runtime.h>
#include <cuda_fp16.h>
#include <cstdint>

// Problem constants
#define BATCH 4
#define SEQ   4096
#define DIM   1024
#define NHEAD 16
#define HDIM  64
#define WIN   256
#define EXT   128
#define NGRP  (SEQ / WIN)          // 16
#define QKVDIM (3 * DIM)           // 3072
#define MROWS (BATCH * SEQ)        // 16384
#define ATT_SCALE 0.125f           // 64^-0.5

// ---------------- scratch (allocation-free: __device__ globals) ----------------
__device__ __half g_qkvh[(size_t)MROWS * QKVDIM];   // 96 MB
__device__ __half g_xh[(size_t)MROWS * DIM];        // 32 MB
__device__ __half g_wqkvh[(size_t)QKVDIM * DIM];    // 6 MB
__device__ __half g_attnh[(size_t)MROWS * DIM];     // 32 MB
__device__ __half g_wprojh[(size_t)DIM * DIM];      // 2 MB

// ================= PTX helpers (base sm_103: NO 'a'-gated instructions) =================
__device__ __forceinline__ uint32_t smem_u32(const void* p) {
    uint32_t a;
    asm("{ .reg .u64 t; cvta.to.shared.u64 t, %1; cvt.u32.u64 %0, t; }" : "=r"(a) : "l"(p));
    return a;
}
#define CP_ASYNC16(s, g) \
    asm volatile("cp.async.cg.shared.global [%0], [%1], 16;" :: "r"(s), "l"(g))
#define CP_COMMIT() asm volatile("cp.async.commit_group;" ::: "memory")
#define CP_WAIT_GROUP(n) asm volatile("cp.async.wait_group %0;" :: "n"(n) : "memory")

__device__ __forceinline__ void ldm_x4(uint32_t* r, uint32_t a) {
    asm volatile("ldmatrix.sync.aligned.m8n8.x4.shared.b16 {%0,%1,%2,%3}, [%4];"
                 : "=r"(r[0]), "=r"(r[1]), "=r"(r[2]), "=r"(r[3]) : "r"(a));
}
__device__ __forceinline__ void ldm_x4_t(uint32_t* r, uint32_t a) {
    asm volatile("ldmatrix.sync.aligned.m8n8.x4.trans.shared.b16 {%0,%1,%2,%3}, [%4];"
                 : "=r"(r[0]), "=r"(r[1]), "=r"(r[2]), "=r"(r[3]) : "r"(a));
}
__device__ __forceinline__ void ldm_x2(uint32_t* r, uint32_t a) {
    asm volatile("ldmatrix.sync.aligned.m8n8.x2.shared.b16 {%0,%1}, [%2];"
                 : "=r"(r[0]), "=r"(r[1]) : "r"(a));
}
__device__ __forceinline__ void mma_f16(float* d, const uint32_t* a, const uint32_t* b) {
    asm volatile("mma.sync.aligned.m16n8k16.row.col.f32.f16.f16.f32 "
                 "{%0,%1,%2,%3}, {%4,%5,%6,%7}, {%8,%9}, {%0,%1,%2,%3};"
                 : "+f"(d[0]), "+f"(d[1]), "+f"(d[2]), "+f"(d[3])
                 : "r"(a[0]), "r"(a[1]), "r"(a[2]), "r"(a[3]), "r"(b[0]), "r"(b[1]));
}
__device__ __forceinline__ uint32_t pack2(float a, float b) {
    __half2 h = __floats2half2_rn(a, b);
    return *(uint32_t*)&h;
}

// ---------------- fused convert fp32 -> fp16 (x, w_qkv, w_proj in one grid) ----
#define CVT_N4_X   (MROWS * DIM / 4)          // 4194304
#define CVT_N4_WQ  (QKVDIM * DIM / 4)         // 786432
#define CVT_N4_WP  (DIM * DIM / 4)            // 262144
#define CVT_N4_ALL (CVT_N4_X + CVT_N4_WQ + CVT_N4_WP)

__global__ void k_cvt3(const float* __restrict__ x, const float* __restrict__ wq,
                       const float* __restrict__ wp, __half* __restrict__ xo,
                       __half* __restrict__ wqo, __half* __restrict__ wpo) {
    int i = blockIdx.x * blockDim.x + threadIdx.x;
    const float* in;
    __half* out;
    int j = i;
    if (j < CVT_N4_X) { in = x; out = xo; }
    else if ((j -= CVT_N4_X) < CVT_N4_WQ) { in = wq; out = wqo; }
    else if ((j -= CVT_N4_WQ) < CVT_N4_WP) { in = wp; out = wpo; }
    else return;
    float4 v = ((const float4*)in)[j];
    ((uint2*)out)[j] = make_uint2(pack2(v.x, v.y), pack2(v.z, v.w));
}

// ---------------- HMMA fp16 GEMM (exact R9 mainloop — best measured) ----------------
// C = A[M][K] * B[N][K]^T + bias. 128x128 CTA tile, K-chunk 64,
// 8 warps (2Mx4N, warp 64x32), 3-stage cp.async ring, 2 CTAs/SM.
// Tile layout: 128 rows x 128B, swizzle: off = r*128 + ((c16 ^ (r&7))<<4).
#define GT_TILE   16384                       // one 128x64 fp16 tile
#define GT_BUF    (2 * GT_TILE)               // A + B = 32 KB per stage
#define GT_STAGES 3
#define GT_TOTAL  (GT_STAGES * GT_BUF)        // 96 KB

template <bool HALF_OUT>
__global__ __launch_bounds__(256, 2) void k_gemm_hmma(
    const __half* __restrict__ A, const __half* __restrict__ B,
    const float* __restrict__ bias, float* __restrict__ C,
    __half* __restrict__ Ch, int M, int N, int K) {
    extern __shared__ char smem[];
    const uint32_t sb = smem_u32(smem);
    const int tid = threadIdx.x;
    const int wid = tid >> 5, l = tid & 31;
    const int bm = blockIdx.y * 128;
    const int bn = blockIdx.x * 128;
    const int wm = (wid >> 2) * 64;
    const int wn = (wid & 3) * 32;

    float acc[4][4][4];
    #pragma unroll
    for (int a = 0; a < 4; a++)
        #pragma unroll
        for (int b = 0; b < 4; b++)
            #pragma unroll
            for (int c = 0; c < 4; c++) acc[a][b][c] = 0.f;

    const int NCH = K >> 6;                   // chunks of 64

    auto load_chunk = [&](int c, int buf) {
        const int k0 = c * 64;
        const uint32_t sbase = sb + buf * GT_BUF;
        #pragma unroll
        for (int j = 0; j < 8; j++) {
            int i = tid + j * 256;            // 0..2047
            int t = i >> 10;                  // 0 = A, 1 = B
            int idx = i & 1023;
            int row = idx >> 3, ch = idx & 7;
            uint32_t soff = row * 128 + ((ch ^ (row & 7)) << 4);
            const __half* src = (t ? B : A)
                + (size_t)((t ? bn : bm) + row) * K + k0 + ch * 8;
            CP_ASYNC16(sbase + t * GT_TILE + soff, src);
        }
    };

    auto compute = [&](int buf) {
        const uint32_t sbase = sb + buf * GT_BUF;
        #pragma unroll
        for (int ks = 0; ks < 4; ks++) {
            uint32_t ah[4][4], bh[4][2];
            const int ar_l = wm + ((l >> 3) & 1) * 8 + (l & 7);
            const int ach = 2 * ks + (l >> 4);
            #pragma unroll
            for (int mf = 0; mf < 4; mf++) {
                int r = ar_l + mf * 16;
                ldm_x4(ah[mf], sbase + r * 128 + ((ach ^ (r & 7)) << 4));
            }
            const int l16 = l & 15;
            const int br_l = wn + (l16 & 7);
            const int bch = 2 * ks + (l16 >> 3);
            #pragma unroll
            for (int nf = 0; nf < 4; nf++) {
                int r = br_l + nf * 8;
                ldm_x2(bh[nf], sbase + GT_TILE + r * 128 + ((bch ^ (r & 7)) << 4));
            }
            #pragma unroll
            for (int mf = 0; mf < 4; mf++)
                #pragma unroll
                for (int nf = 0; nf < 4; nf++)
                    mma_f16(acc[mf][nf], ah[mf], bh[nf]);
        }
    };

    load_chunk(0, 0);
    CP_COMMIT();
    load_chunk(1, 1);
    CP_COMMIT();
    for (int c = 0; c < NCH; c++) {
        CP_WAIT_GROUP(1);
        __syncthreads();
        if (c + 2 < NCH) load_chunk(c + 2, (c + 2) % 3);
        CP_COMMIT();
        compute(c % 3);
    }

    const int rbase = bm + wm + (l >> 2);
    const int cbase = bn + wn + (l & 3) * 2;
    #pragma unroll
    for (int mf = 0; mf < 4; mf++) {
        int r0 = rbase + mf * 16;
        #pragma unroll
        for (int nf = 0; nf < 4; nf++) {
            int cc = cbase + nf * 8;
            float2 bv = *(const float2*)&bias[cc];
            float v00 = acc[mf][nf][0] + bv.x, v01 = acc[mf][nf][1] + bv.y;
            float v10 = acc[mf][nf][2] + bv.x, v11 = acc[mf][nf][3] + bv.y;
            if (HALF_OUT) {
                *(uint32_t*)(Ch + (size_t)r0 * N + cc) = pack2(v00, v01);
                *(uint32_t*)(Ch + (size_t)(r0 + 8) * N + cc) = pack2(v10, v11);
            } else {
                *(float2*)&C[(size_t)r0 * N + cc] = make_float2(v00, v01);
                *(float2*)&C[(size_t)(r0 + 8) * N + cc] = make_float2(v10, v11);
            }
        }
    }
}

// ---------------- HMMA local attention (fp16, exact R9) ----------------
// CTA = 128 q rows of one (b,h,group-half). 8 warps x 16 q rows.
// 3-stage KV ring (16 KB/stage), one barrier per 64-key chunk. 2 CTAs/SM.
#define AT_SMEM (16384 + 3 * 16384)

__global__ __launch_bounds__(256, 2) void k_attn_hmma(
    const __half* __restrict__ qg, __half* __restrict__ og) {
    extern __shared__ char smem[];
    const uint32_t sb = smem_u32(smem);
    const int half_ = blockIdx.x & 1, g = blockIdx.x >> 1;
    const int h = blockIdx.y, b = blockIdx.z;
    const int tid = threadIdx.x, wid = tid >> 5, l = tid & 31;
    const int qrow0 = b * SEQ + g * WIN + half_ * 128;
    const int wq = wid * 16;

    #pragma unroll
    for (int j = 0; j < 4; j++) {
        int idx = tid + j * 256;
        int row = idx >> 3, ch = idx & 7;
        const __half* src = qg + (size_t)(qrow0 + row) * QKVDIM + h * HDIM + ch * 8;
        CP_ASYNC16(sb + row * 128 + ((ch ^ (row & 7)) << 4), src);
    }

    auto stage_kv = [&](int c, int buf) {
        const int kr0 = b * SEQ + g * WIN - EXT + c * 64;
        const uint32_t base = sb + 16384 + buf * 16384;
        #pragma unroll
        for (int j = 0; j < 4; j++) {
            int i = tid + j * 256;
            int t = i >> 9;                   // 0 = K, 1 = V
            int idx = i & 511;
            int row = idx >> 3, ch = idx & 7;
            const __half* src = qg + (size_t)(kr0 + row) * QKVDIM
                + (t ? 2 * DIM : DIM) + h * HDIM + ch * 8;
            CP_ASYNC16(base + t * 8192 + row * 128 + ((ch ^ (row & 7)) << 4), src);
        }
    };

    uint32_t qf[4][4];
    float o[8][4];
    #pragma unroll
    for (int nf = 0; nf < 8; nf++)
        #pragma unroll
        for (int j = 0; j < 4; j++) o[nf][j] = 0.f;
    float ma = -1e30f, mb = -1e30f, la = 0.f, lb = 0.f;

    const int c0 = (g == 0) ? 2 : 0;
    const int c1 = (g == NGRP - 1) ? 6 : 8;
    const int nch = c1 - c0;

    stage_kv(c0, 0);
    CP_COMMIT();
    if (nch > 1) stage_kv(c0 + 1, 1);
    CP_COMMIT();

    for (int it = 0; it < nch; it++) {
        CP_WAIT_GROUP(1);
        __syncthreads();
        {
            int nxt = it + 2;
            if (nxt < nch) stage_kv(c0 + nxt, nxt % 3);
            CP_COMMIT();
        }
        if (it == 0) {
            #pragma unroll
            for (int ks = 0; ks < 4; ks++) {
                int r = wq + (l & 7) + ((l >> 3) & 1) * 8;
                int c = 2 * ks + ((l >> 4) & 1);
                ldm_x4(qf[ks], sb + r * 128 + ((c ^ (r & 7)) << 4));
            }
        }
        const uint32_t kb = sb + 16384 + (it % 3) * 16384;

        // ---- QK: S[16q x 64k] per warp ----
        float s[8][4];
        #pragma unroll
        for (int nf = 0; nf < 8; nf++)
            #pragma unroll
            for (int j = 0; j < 4; j++) s[nf][j] = 0.f;
        #pragma unroll
        for (int ks = 0; ks < 4; ks++) {
            const int r = (l & 7) + ((l >> 4) & 1) * 8;
            const int c = 2 * ks + ((l >> 3) & 1);
            #pragma unroll
            for (int np = 0; np < 4; np++) {
                int rr = np * 16 + r;
                uint32_t kf[4];
                ldm_x4(kf, kb + rr * 128 + ((c ^ (rr & 7)) << 4));
                mma_f16(s[2 * np],     qf[ks], kf);
                mma_f16(s[2 * np + 1], qf[ks], kf + 2);
            }
        }

        // ---- online softmax ----
        float mxa = -1e30f, mxb = -1e30f;
        #pragma unroll
        for (int nf = 0; nf < 8; nf++) {
            mxa = fmaxf(mxa, fmaxf(s[nf][0], s[nf][1]));
            mxb = fmaxf(mxb, fmaxf(s[nf][2], s[nf][3]));
        }
        mxa = fmaxf(mxa, __shfl_xor_sync(0xffffffffu, mxa, 1));
        mxa = fmaxf(mxa, __shfl_xor_sync(0xffffffffu, mxa, 2));
        mxb = fmaxf(mxb, __shfl_xor_sync(0xffffffffu, mxb, 1));
        mxb = fmaxf(mxb, __shfl_xor_sync(0xffffffffu, mxb, 2));
        float nma = fmaxf(ma, mxa), nmb = fmaxf(mb, mxb);
        float ca = __expf((ma - nma) * ATT_SCALE);
        float cb = __expf((mb - nmb) * ATT_SCALE);
        ma = nma; mb = nmb;
        la *= ca; lb *= cb;
        #pragma unroll
        for (int nf = 0; nf < 8; nf++) {
            s[nf][0] = __expf((s[nf][0] - ma) * ATT_SCALE);
            s[nf][1] = __expf((s[nf][1] - ma) * ATT_SCALE);
            s[nf][2] = __expf((s[nf][2] - mb) * ATT_SCALE);
            s[nf][3] = __expf((s[nf][3] - mb) * ATT_SCALE);
            la += s[nf][0] + s[nf][1];
            lb += s[nf][2] + s[nf][3];
            o[nf][0] *= ca; o[nf][1] *= ca;
            o[nf][2] *= cb; o[nf][3] *= cb;
        }

        // ---- pack P into A-frags ----
        uint32_t pf[4][4];
        #pragma unroll
        for (int j = 0; j < 4; j++) {
            pf[j][0] = pack2(s[2 * j][0],     s[2 * j][1]);
            pf[j][1] = pack2(s[2 * j][2],     s[2 * j][3]);
            pf[j][2] = pack2(s[2 * j + 1][0], s[2 * j + 1][1]);
            pf[j][3] = pack2(s[2 * j + 1][2], s[2 * j + 1][3]);
        }

        // ---- PV: O += P * V ----
        #pragma unroll
        for (int ks = 0; ks < 4; ks++) {
            const int r = ks * 16 + (l & 7) + ((l >> 3) & 1) * 8;
            const int c = (l >> 4) & 1;
            #pragma unroll
            for (int dp = 0; dp < 4; dp++) {
                int cc = 2 * dp + c;
                uint32_t vf[4];
                ldm_x4_t(vf, kb + 8192 + r * 128 + ((cc ^ (r & 7)) << 4));
                mma_f16(o[2 * dp],     pf[ks], vf);
                mma_f16(o[2 * dp + 1], pf[ks], vf + 2);
            }
        }
    }

    // ---- epilogue ----
    la += __shfl_xor_sync(0xffffffffu, la, 1);
    la += __shfl_xor_sync(0xffffffffu, la, 2);
    lb += __shfl_xor_sync(0xffffffffu, lb, 1);
    lb += __shfl_xor_sync(0xffffffffu, lb, 2);
    const float ia = 1.f / la, ib = 1.f / lb;
    const int ra = qrow0 + wq + (l >> 2);
    const int rb = ra + 8;
    const int colb = h * HDIM + 2 * (l & 3);
    #pragma unroll
    for (int nf = 0; nf < 8; nf++) {
        int cc = colb + nf * 8;
        *(uint32_t*)(og + (size_t)ra * DIM + cc) = pack2(o[nf][0] * ia, o[nf][1] * ia);
        *(uint32_t*)(og + (size_t)rb * DIM + cc) = pack2(o[nf][2] * ib, o[nf][3] * ib);
    }
}

// ---------------- launch ----------------
extern "C" void kernel_launch(void* const* d_in, const int* in_sizes, int n_in,
                              void* d_out, int out_size) {
    const float* x      = (const float*)d_in[0];
    const float* w_qkv  = (const float*)d_in[1];
    const float* b_qkv  = (const float*)d_in[2];
    const float* w_proj = (const float*)d_in[3];
    const float* b_proj = (const float*)d_in[4];
    float* out = (float*)d_out;

    __half *qh, *xh, *wqh, *ah, *wph;
    cudaGetSymbolAddress((void**)&qh,  g_qkvh);
    cudaGetSymbolAddress((void**)&xh,  g_xh);
    cudaGetSymbolAddress((void**)&wqh, g_wqkvh);
    cudaGetSymbolAddress((void**)&ah,  g_attnh);
    cudaGetSymbolAddress((void**)&wph, g_wprojh);

    cudaFuncSetAttribute(k_gemm_hmma<true>,  cudaFuncAttributeMaxDynamicSharedMemorySize, GT_TOTAL);
    cudaFuncSetAttribute(k_gemm_hmma<false>, cudaFuncAttributeMaxDynamicSharedMemorySize, GT_TOTAL);
    cudaFuncSetAttribute(k_attn_hmma, cudaFuncAttributeMaxDynamicSharedMemorySize, AT_SMEM);

    // 1. fused fp32 -> fp16 converts (single launch)
    k_cvt3<<<(CVT_N4_ALL + 255) / 256, 256>>>(x, w_qkv, w_proj, xh, wqh, wph);

    // 2. QKV projection -> fp16
    k_gemm_hmma<true><<<dim3(QKVDIM / 128, MROWS / 128), 256, GT_TOTAL>>>(
        xh, wqh, b_qkv, nullptr, qh, MROWS, QKVDIM, DIM);

    // 3. local windowed attention -> fp16
    k_attn_hmma<<<dim3(NGRP * 2, NHEAD, BATCH), 256, AT_SMEM>>>(qh, ah);

    // 4. output projection -> fp32 out
    k_gemm_hmma<false><<<dim3(DIM / 128, MROWS / 128), 256, GT_TOTAL>>>(
        ah, wph, b_proj, out, nullptr, MROWS, DIM, DIM);
}